// round 3
// baseline (speedup 1.0000x reference)
#include <cuda_runtime.h>
#include <cstddef>

#define N_NODES 10000
#define E_EDGES 160000
#define P_PAIRS 20000
#define D_IN    256
#define D_H     512
#define D4      2048
#define NCLS    40

// ---------------- scratch (static device globals; no allocs) ----------------
__device__ unsigned g_aggU[(size_t)N_NODES * D_H];
__device__ float    g_agg [(size_t)N_NODES * D_H];
__device__ float    g_h   [(size_t)N_NODES * D_H];
__device__ float    g_bnx [(size_t)N_NODES * D_H];
__device__ float    g_t   [(size_t)N_NODES * D_H];
__device__ float    g_z   [(size_t)P_PAIRS * D4];
__device__ float    g_zz  [(size_t)P_PAIRS * D4];
__device__ float    g_part[2 * 80 * D_H];
__device__ float    g_mu[D_H], g_rstd[D_H];
__device__ int      g_ps[N_NODES], g_pd[N_NODES];

__device__ __forceinline__ unsigned f2u_mono(float v) {
    int iv = __float_as_int(v);
    return (iv >= 0) ? ((unsigned)iv | 0x80000000u) : ~(unsigned)iv;
}

// segment max via order-preserving unsigned encoding + atomicMax.
// One thread handles 4 consecutive feature dims of one edge (D % 4 == 0).
__global__ void k_scatter_max4(const float* __restrict__ feat,
                               const int* __restrict__ src,
                               const int* __restrict__ dst,
                               unsigned* __restrict__ aggU, int E, int D) {
    long long i = (long long)blockIdx.x * blockDim.x + threadIdx.x;
    int Dq = D >> 2;
    if (i >= (long long)E * Dq) return;
    int e = (int)(i / Dq);
    int dq = (int)(i - (long long)e * Dq);
    int s = src[e], t = dst[e];
    float4 v = *(const float4*)(feat + (size_t)s * D + dq * 4);
    unsigned* a = aggU + (size_t)t * D + dq * 4;
    atomicMax(a + 0, f2u_mono(v.x));
    atomicMax(a + 1, f2u_mono(v.y));
    atomicMax(a + 2, f2u_mono(v.z));
    atomicMax(a + 3, f2u_mono(v.w));
}

__global__ void k_decode(const unsigned* __restrict__ aggU, float* __restrict__ agg, int n) {
    int i = blockIdx.x * blockDim.x + threadIdx.x;
    if (i >= n) return;
    unsigned u = aggU[i];
    float v;
    if (u == 0u) v = 0.0f;                 // empty segment -> 0 (matches jnp.where(isfinite))
    else if (u & 0x80000000u) v = __int_as_float((int)(u & 0x7fffffffu));
    else v = __int_as_float((int)~u);
    agg[i] = v;
}

// ---------------- SGEMM: C[M,N] = A[M,K] @ B[N,K]^T (+bias) (+accum) ----------------
// 128x128 tile, BK=8, 256 threads, 8x8 per-thread register tile.
__global__ void __launch_bounds__(256) sgemm_nt(
    const float* __restrict__ A, const float* __restrict__ B,
    const float* __restrict__ bias, float* __restrict__ C,
    int M, int N, int K, int accum)
{
    __shared__ float As[8][128];
    __shared__ float Bs[8][128];
    const int tid = threadIdx.x;
    const int m0 = blockIdx.y * 128;
    const int n0 = blockIdx.x * 128;
    const int lr = tid >> 1;           // 0..127
    const int lk = (tid & 1) << 2;     // 0 or 4
    const int tx = tid & 15;
    const int ty = tid >> 4;

    float acc[8][8];
#pragma unroll
    for (int i = 0; i < 8; i++)
#pragma unroll
        for (int j = 0; j < 8; j++) acc[i][j] = 0.0f;

    const int am = m0 + lr;
    const int bn = n0 + lr;
    const bool aval = am < M;
    const bool bval = bn < N;
    const float* Aptr = A + (size_t)am * K + lk;
    const float* Bptr = B + (size_t)bn * K + lk;

    for (int k0 = 0; k0 < K; k0 += 8) {
        float4 av = make_float4(0.f, 0.f, 0.f, 0.f);
        float4 bv = make_float4(0.f, 0.f, 0.f, 0.f);
        if (aval) av = *(const float4*)(Aptr + k0);
        if (bval) bv = *(const float4*)(Bptr + k0);
        As[lk + 0][lr] = av.x; As[lk + 1][lr] = av.y;
        As[lk + 2][lr] = av.z; As[lk + 3][lr] = av.w;
        Bs[lk + 0][lr] = bv.x; Bs[lk + 1][lr] = bv.y;
        Bs[lk + 2][lr] = bv.z; Bs[lk + 3][lr] = bv.w;
        __syncthreads();
#pragma unroll
        for (int k = 0; k < 8; k++) {
            float a[8], bb[8];
            *(float4*)&a[0]  = *(const float4*)&As[k][ty * 4];
            *(float4*)&a[4]  = *(const float4*)&As[k][64 + ty * 4];
            *(float4*)&bb[0] = *(const float4*)&Bs[k][tx * 4];
            *(float4*)&bb[4] = *(const float4*)&Bs[k][64 + tx * 4];
#pragma unroll
            for (int i = 0; i < 8; i++)
#pragma unroll
                for (int j = 0; j < 8; j++)
                    acc[i][j] = fmaf(a[i], bb[j], acc[i][j]);
        }
        __syncthreads();
    }

#pragma unroll
    for (int i = 0; i < 8; i++) {
        int m = m0 + ((i < 4) ? (ty * 4 + i) : (64 + ty * 4 + (i - 4)));
        if (m >= M) continue;
#pragma unroll
        for (int j = 0; j < 8; j++) {
            int n = n0 + ((j < 4) ? (tx * 4 + j) : (64 + tx * 4 + (j - 4)));
            if (n >= N) continue;
            float v = acc[i][j];
            if (bias) v += bias[n];
            size_t off = (size_t)m * N + n;
            if (accum) v += C[off];
            C[off] = v;
        }
    }
}

// ---------------- batchnorm (axis-0, biased var), two-pass deterministic ----------------
__global__ void k_col_partial(const float* __restrict__ X, float* __restrict__ part, int M, int D) {
    int blk = blockIdx.x;
    int r0 = blk * 128;
    int r1 = min(r0 + 128, M);
    for (int c = threadIdx.x; c < D; c += blockDim.x) {
        float s = 0.f, s2 = 0.f;
        for (int r = r0; r < r1; r++) {
            float v = X[(size_t)r * D + c];
            s += v; s2 += v * v;
        }
        part[(size_t)(2 * blk) * D + c] = s;
        part[(size_t)(2 * blk + 1) * D + c] = s2;
    }
}
__global__ void k_col_finalize(const float* __restrict__ part, int nblk, int M, int D,
                               float* __restrict__ mu, float* __restrict__ rstd) {
    int c = blockIdx.x * blockDim.x + threadIdx.x;
    if (c >= D) return;
    float s = 0.f, s2 = 0.f;
    for (int b = 0; b < nblk; b++) {
        s  += part[(size_t)(2 * b) * D + c];
        s2 += part[(size_t)(2 * b + 1) * D + c];
    }
    float m = s / M;
    float var = s2 / M - m * m;
    mu[c] = m;
    rstd[c] = rsqrtf(var + 1e-5f);
}
__global__ void k_bn_apply(const float* __restrict__ X, const float* __restrict__ mu,
                           const float* __restrict__ rstd, const float* __restrict__ g,
                           const float* __restrict__ b, float* __restrict__ Y, int n, int D) {
    int i = blockIdx.x * blockDim.x + threadIdx.x;
    if (i >= n) return;
    int c = i & (D - 1);   // D is a power of two (512)
    Y[i] = (X[i] - mu[c]) * rstd[c] * g[c] + b[c];
}

// ---------------- pair-index scatter semantics (last update wins, dst after src) ----------------
__global__ void k_pair_argmax(const int* __restrict__ sp, const int* __restrict__ dp,
                              int* __restrict__ ps, int* __restrict__ pd, int P) {
    int p = blockIdx.x * blockDim.x + threadIdx.x;
    if (p >= P) return;
    atomicMax(&ps[sp[p]], p);
    atomicMax(&pd[dp[p]], p);
}

__global__ void k_assemble_x(const float* __restrict__ bnx, const float* __restrict__ h1c,
                             const float* __restrict__ h2c, const int* __restrict__ ps,
                             const int* __restrict__ pd, float* __restrict__ xout) {
    int i = blockIdx.x * blockDim.x + threadIdx.x;
    if (i >= N_NODES * 1024) return;
    int node = i >> 10, j = i & 1023;
    float v;
    if (j < 512) {
        int d = pd[node];
        if (d >= 0) v = h2c[(size_t)d * 512 + j];
        else {
            int s = ps[node];
            v = (s >= 0) ? h1c[(size_t)s * 512 + j] : bnx[(size_t)node * 512 + j];
        }
    } else {
        v = bnx[(size_t)node * 512 + (j - 512)];
    }
    xout[i] = v;
}

__global__ void k_gather_z(const float* __restrict__ xout, const int* __restrict__ sp,
                           const int* __restrict__ dp, float* __restrict__ z) {
    long long i = (long long)blockIdx.x * blockDim.x + threadIdx.x;
    if (i >= (long long)P_PAIRS * D4) return;
    int p = (int)(i >> 11), j = (int)(i & 2047);
    int node = (j < 1024) ? sp[p] : dp[p];
    z[i] = xout[(size_t)node * 1024 + (j & 1023)];
}

// ---------------- row layernorm + relu (in place) ----------------
template <int VPT>
__global__ void __launch_bounds__(256) k_row_ln_relu(float* __restrict__ X,
                                                     const float* __restrict__ g,
                                                     const float* __restrict__ b, int W) {
    int row = blockIdx.x;
    float* xr = X + (size_t)row * W;
    float v[VPT];
    float s = 0.f, s2 = 0.f;
#pragma unroll
    for (int i = 0; i < VPT; i++) {
        v[i] = xr[threadIdx.x + i * 256];
        s += v[i]; s2 += v[i] * v[i];
    }
#pragma unroll
    for (int o = 16; o > 0; o >>= 1) {
        s  += __shfl_xor_sync(0xffffffffu, s, o);
        s2 += __shfl_xor_sync(0xffffffffu, s2, o);
    }
    __shared__ float sh[16];
    int warp = threadIdx.x >> 5, lane = threadIdx.x & 31;
    if (lane == 0) { sh[warp] = s; sh[warp + 8] = s2; }
    __syncthreads();
    s = 0.f; s2 = 0.f;
#pragma unroll
    for (int w = 0; w < 8; w++) { s += sh[w]; s2 += sh[w + 8]; }
    float mu = s / W;
    float var = s2 / W - mu * mu;
    float rs = rsqrtf(var + 1e-5f);
#pragma unroll
    for (int i = 0; i < VPT; i++) {
        int c = threadIdx.x + i * 256;
        float y = (v[i] - mu) * rs * g[c] + b[c];
        xr[c] = fmaxf(y, 0.f);
    }
}

// ---------------- launcher ----------------
#define LP1D(kern, n, ...) kern<<<((int)(((long long)(n) + 255) / 256)), 256>>>(__VA_ARGS__)

static inline void* sym(const void* s) {
    void* p = nullptr;
    cudaGetSymbolAddress(&p, s);
    return p;
}

extern "C" void kernel_launch(void* const* d_in, const int* in_sizes, int n_in,
                              void* d_out, int out_size) {
    const float* x_feat = (const float*)d_in[0];
    const int*   edge   = (const int*)d_in[1];
    const int*   pairs  = (const int*)d_in[2];
    const float* h1c    = (const float*)d_in[3];
    const float* h2c    = (const float*)d_in[4];
    const float* W1l = (const float*)d_in[5];
    const float* b1l = (const float*)d_in[6];
    const float* W1r = (const float*)d_in[7];
    const float* bn1_g = (const float*)d_in[8];
    const float* bn1_b = (const float*)d_in[9];
    const float* W2l = (const float*)d_in[10];
    const float* b2l = (const float*)d_in[11];
    const float* W2r = (const float*)d_in[12];
    const float* bn_g = (const float*)d_in[13];
    const float* bn_b = (const float*)d_in[14];
    const float* Wp  = (const float*)d_in[15];
    const float* bp  = (const float*)d_in[16];
    const float* pln_g = (const float*)d_in[17];
    const float* pln_b = (const float*)d_in[18];
    const float* Wpc = (const float*)d_in[19];
    const float* bpc = (const float*)d_in[20];
    const float* We  = (const float*)d_in[21];
    const float* be  = (const float*)d_in[22];
    const float* Wnm = (const float*)d_in[23];
    const float* bnm = (const float*)d_in[24];
    const float* nln_g = (const float*)d_in[25];
    const float* nln_b = (const float*)d_in[26];
    const float* Wnc = (const float*)d_in[27];
    const float* bnc = (const float*)d_in[28];

    const int* e_src = edge;
    const int* e_dst = edge + E_EDGES;
    const int* p_src = pairs;
    const int* p_dst = pairs + P_PAIRS;

    float* out = (float*)d_out;
    float* out_nl  = out;                  // node_logit   [10000,40]
    float* out_pl  = out + 400000;         // pairs_logit  [20000,40]
    float* out_pcl = out + 1200000;        // pairs_cons   [20000,2]
    float* out_x   = out + 1240000;        // x            [10000,1024]
    float* out_gx  = out + 11480000;       // gnn_x        [10000,512]

    unsigned* aggU = (unsigned*)sym(g_aggU);
    float* agg  = (float*)sym(g_agg);
    float* h    = (float*)sym(g_h);
    float* bnx  = (float*)sym(g_bnx);
    float* tbuf = (float*)sym(g_t);
    float* z    = (float*)sym(g_z);
    float* zz   = (float*)sym(g_zz);
    float* part = (float*)sym(g_part);
    float* mu   = (float*)sym(g_mu);
    float* rstd = (float*)sym(g_rstd);
    int* ps = (int*)sym(g_ps);
    int* pd = (int*)sym(g_pd);

    const int nblk_stats = (N_NODES + 127) / 128;  // 79

    // ---- SAGE layer 1 ----
    cudaMemsetAsync(aggU, 0x00, (size_t)N_NODES * D_IN * sizeof(unsigned));
    LP1D(k_scatter_max4, (long long)E_EDGES * (D_IN / 4), x_feat, e_src, e_dst, aggU, E_EDGES, D_IN);
    LP1D(k_decode, N_NODES * D_IN, aggU, agg, N_NODES * D_IN);
    {
        dim3 grid((D_H + 127) / 128, (N_NODES + 127) / 128);
        sgemm_nt<<<grid, 256>>>(agg,    W1l, b1l,     h, N_NODES, D_H, D_IN, 0);
        sgemm_nt<<<grid, 256>>>(x_feat, W1r, nullptr, h, N_NODES, D_H, D_IN, 1);
    }
    k_col_partial<<<nblk_stats, 256>>>(h, part, N_NODES, D_H);
    k_col_finalize<<<2, 256>>>(part, nblk_stats, N_NODES, D_H, mu, rstd);
    LP1D(k_bn_apply, N_NODES * D_H, h, mu, rstd, bn1_g, bn1_b, h, N_NODES * D_H, D_H);

    // ---- SAGE layer 2 ----
    cudaMemsetAsync(aggU, 0x00, (size_t)N_NODES * D_H * sizeof(unsigned));
    LP1D(k_scatter_max4, (long long)E_EDGES * (D_H / 4), h, e_src, e_dst, aggU, E_EDGES, D_H);
    LP1D(k_decode, N_NODES * D_H, aggU, agg, N_NODES * D_H);
    {
        dim3 grid((D_H + 127) / 128, (N_NODES + 127) / 128);
        sgemm_nt<<<grid, 256>>>(agg, W2l, b2l,     out_gx, N_NODES, D_H, D_H, 0);
        sgemm_nt<<<grid, 256>>>(h,   W2r, nullptr, out_gx, N_NODES, D_H, D_H, 1);
    }
    k_col_partial<<<nblk_stats, 256>>>(out_gx, part, N_NODES, D_H);
    k_col_finalize<<<2, 256>>>(part, nblk_stats, N_NODES, D_H, mu, rstd);
    LP1D(k_bn_apply, N_NODES * D_H, out_gx, mu, rstd, bn_g, bn_b, bnx, N_NODES * D_H, D_H);

    // ---- x assembly (scatter with last-wins, dst over src) ----
    cudaMemsetAsync(ps, 0xFF, N_NODES * sizeof(int));   // -1
    cudaMemsetAsync(pd, 0xFF, N_NODES * sizeof(int));   // -1
    LP1D(k_pair_argmax, P_PAIRS, p_src, p_dst, ps, pd, P_PAIRS);
    LP1D(k_assemble_x, N_NODES * 1024, bnx, h1c, h2c, ps, pd, out_x);

    // ---- pair head ----
    LP1D(k_gather_z, (long long)P_PAIRS * D4, out_x, p_src, p_dst, z);
    {
        dim3 grid((D4 + 127) / 128, (P_PAIRS + 127) / 128);
        sgemm_nt<<<grid, 256>>>(z, Wp, bp, zz, P_PAIRS, D4, D4, 0);
    }
    k_row_ln_relu<8><<<P_PAIRS, 256>>>(zz, pln_g, pln_b, D4);
    {
        dim3 grid(1, (P_PAIRS + 127) / 128);
        sgemm_nt<<<grid, 256>>>(zz, Wpc, bpc, out_pl,  P_PAIRS, NCLS, D4, 0);
        sgemm_nt<<<grid, 256>>>(zz, We,  be,  out_pcl, P_PAIRS, 2,    D4, 0);
    }

    // ---- node head ----
    {
        dim3 grid((D_H + 127) / 128, (N_NODES + 127) / 128);
        sgemm_nt<<<grid, 256>>>(out_x, Wnm, bnm, tbuf, N_NODES, D_H, 1024, 0);
    }
    k_row_ln_relu<2><<<N_NODES, 256>>>(tbuf, nln_g, nln_b, D_H);
    {
        dim3 grid(1, (N_NODES + 127) / 128);
        sgemm_nt<<<grid, 256>>>(tbuf, Wnc, bnc, out_nl, N_NODES, NCLS, D_H, 0);
    }
}

// round 5
// speedup vs baseline: 1.5255x; 1.5255x over previous
#include <cuda_runtime.h>
#include <cuda_bf16.h>
#include <cstdint>
#include <cstddef>

#define N_NODES 10000
#define E_EDGES 160000
#define P_PAIRS 20000
#define D_IN    256
#define D_H     512
#define D4      2048
#define NCLS    40

// ---------------- scratch (static device globals; no allocs) ----------------
__device__ unsigned g_aggU[(size_t)N_NODES * D_H];
__device__ float    g_agg [(size_t)N_NODES * D_H];
__device__ float    g_h   [(size_t)N_NODES * D_H];
__device__ float    g_bnx [(size_t)N_NODES * D_H];
__device__ float    g_t   [(size_t)N_NODES * D_H];
__device__ float    g_zz  [(size_t)P_PAIRS * D4];
__device__ float    g_part[2 * 80 * D_H];
__device__ float    g_mu[D_H], g_rstd[D_H];
__device__ int      g_ps[N_NODES], g_pd[N_NODES];
// split-bf16 operands for the big pair GEMM
__device__ __nv_bfloat16 g_zhi[(size_t)P_PAIRS * D4];
__device__ __nv_bfloat16 g_zlo[(size_t)P_PAIRS * D4];
__device__ __nv_bfloat16 g_wphi[(size_t)D4 * D4];
__device__ __nv_bfloat16 g_wplo[(size_t)D4 * D4];

// ---------------- PTX helpers (sm_80-compatible only) ----------------
__device__ __forceinline__ uint32_t smem_u32(const void* p) {
    uint32_t a;
    asm("{ .reg .u64 t; cvta.to.shared.u64 t, %1; cvt.u32.u64 %0, t; }" : "=r"(a) : "l"(p));
    return a;
}
__device__ __forceinline__ void cp16(uint32_t s, const void* g) {
    asm volatile("cp.async.cg.shared.global [%0], [%1], 16;\n" :: "r"(s), "l"(g));
}
#define CP_COMMIT() asm volatile("cp.async.commit_group;\n" ::: "memory")
#define CP_WAIT1()  asm volatile("cp.async.wait_group 1;\n" ::: "memory")
#define CP_WAIT0()  asm volatile("cp.async.wait_group 0;\n" ::: "memory")

__device__ __forceinline__ void ldsm4(uint32_t& r0, uint32_t& r1, uint32_t& r2, uint32_t& r3, uint32_t addr) {
    asm volatile("ldmatrix.sync.aligned.m8n8.x4.shared.b16 {%0,%1,%2,%3}, [%4];"
                 : "=r"(r0), "=r"(r1), "=r"(r2), "=r"(r3) : "r"(addr));
}
__device__ __forceinline__ void mma_bf16(float& d0, float& d1, float& d2, float& d3,
                                         uint32_t a0, uint32_t a1, uint32_t a2, uint32_t a3,
                                         uint32_t b0, uint32_t b1) {
    asm volatile("mma.sync.aligned.m16n8k16.row.col.f32.bf16.bf16.f32 "
                 "{%0,%1,%2,%3}, {%4,%5,%6,%7}, {%8,%9}, {%0,%1,%2,%3};"
                 : "+f"(d0), "+f"(d1), "+f"(d2), "+f"(d3)
                 : "r"(a0), "r"(a1), "r"(a2), "r"(a3), "r"(b0), "r"(b1));
}

__device__ __forceinline__ void split1(float v, __nv_bfloat16& h, __nv_bfloat16& l) {
    h = __float2bfloat16_rn(v);
    l = __float2bfloat16_rn(v - __bfloat162float(h));
}

// ---------------- graph helpers ----------------
__device__ __forceinline__ unsigned f2u_mono(float v) {
    int iv = __float_as_int(v);
    return (iv >= 0) ? ((unsigned)iv | 0x80000000u) : ~(unsigned)iv;
}

__global__ void k_scatter_max4(const float* __restrict__ feat,
                               const int* __restrict__ src,
                               const int* __restrict__ dst,
                               unsigned* __restrict__ aggU, int E, int D) {
    long long i = (long long)blockIdx.x * blockDim.x + threadIdx.x;
    int Dq = D >> 2;
    if (i >= (long long)E * Dq) return;
    int e = (int)(i / Dq);
    int dq = (int)(i - (long long)e * Dq);
    int s = src[e], t = dst[e];
    float4 v = *(const float4*)(feat + (size_t)s * D + dq * 4);
    unsigned* a = aggU + (size_t)t * D + dq * 4;
    atomicMax(a + 0, f2u_mono(v.x));
    atomicMax(a + 1, f2u_mono(v.y));
    atomicMax(a + 2, f2u_mono(v.z));
    atomicMax(a + 3, f2u_mono(v.w));
}

__global__ void k_decode(const unsigned* __restrict__ aggU, float* __restrict__ agg, int n) {
    int i = blockIdx.x * blockDim.x + threadIdx.x;
    if (i >= n) return;
    unsigned u = aggU[i];
    float v;
    if (u == 0u) v = 0.0f;
    else if (u & 0x80000000u) v = __int_as_float((int)(u & 0x7fffffffu));
    else v = __int_as_float((int)~u);
    agg[i] = v;
}

// ---------------- fp32 SGEMM (small/medium GEMMs) ----------------
__global__ void __launch_bounds__(256) sgemm_nt(
    const float* __restrict__ A, const float* __restrict__ B,
    const float* __restrict__ bias, float* __restrict__ C,
    int M, int N, int K, int accum)
{
    __shared__ float As[8][128];
    __shared__ float Bs[8][128];
    const int tid = threadIdx.x;
    const int m0 = blockIdx.y * 128;
    const int n0 = blockIdx.x * 128;
    const int lr = tid >> 1;
    const int lk = (tid & 1) << 2;
    const int tx = tid & 15;
    const int ty = tid >> 4;

    float acc[8][8];
#pragma unroll
    for (int i = 0; i < 8; i++)
#pragma unroll
        for (int j = 0; j < 8; j++) acc[i][j] = 0.0f;

    const int am = m0 + lr;
    const int bn = n0 + lr;
    const bool aval = am < M;
    const bool bval = bn < N;
    const float* Aptr = A + (size_t)am * K + lk;
    const float* Bptr = B + (size_t)bn * K + lk;

    for (int k0 = 0; k0 < K; k0 += 8) {
        float4 av = make_float4(0.f, 0.f, 0.f, 0.f);
        float4 bv = make_float4(0.f, 0.f, 0.f, 0.f);
        if (aval) av = *(const float4*)(Aptr + k0);
        if (bval) bv = *(const float4*)(Bptr + k0);
        As[lk + 0][lr] = av.x; As[lk + 1][lr] = av.y;
        As[lk + 2][lr] = av.z; As[lk + 3][lr] = av.w;
        Bs[lk + 0][lr] = bv.x; Bs[lk + 1][lr] = bv.y;
        Bs[lk + 2][lr] = bv.z; Bs[lk + 3][lr] = bv.w;
        __syncthreads();
#pragma unroll
        for (int k = 0; k < 8; k++) {
            float a[8], bb[8];
            *(float4*)&a[0]  = *(const float4*)&As[k][ty * 4];
            *(float4*)&a[4]  = *(const float4*)&As[k][64 + ty * 4];
            *(float4*)&bb[0] = *(const float4*)&Bs[k][tx * 4];
            *(float4*)&bb[4] = *(const float4*)&Bs[k][64 + tx * 4];
#pragma unroll
            for (int i = 0; i < 8; i++)
#pragma unroll
                for (int j = 0; j < 8; j++)
                    acc[i][j] = fmaf(a[i], bb[j], acc[i][j]);
        }
        __syncthreads();
    }

#pragma unroll
    for (int i = 0; i < 8; i++) {
        int m = m0 + ((i < 4) ? (ty * 4 + i) : (64 + ty * 4 + (i - 4)));
        if (m >= M) continue;
#pragma unroll
        for (int j = 0; j < 8; j++) {
            int n = n0 + ((j < 4) ? (tx * 4 + j) : (64 + tx * 4 + (j - 4)));
            if (n >= N) continue;
            float v = acc[i][j];
            if (bias) v += bias[n];
            size_t off = (size_t)m * N + n;
            if (accum) v += C[off];
            C[off] = v;
        }
    }
}

// ---------------- split-bf16 x3 tensor-core GEMM via mma.sync ----------------
// C[M,N] = (Ahi+Alo)@(Bhi+Blo)^T + bias, dropping lo*lo. A[M,K], B[N,K] row-major bf16.
// 128x128 tile, BK=32, 8 warps (warp tile 64x32), 2-stage cp.async.
#define GBM 128
#define GBN 128
#define GBK 32
#define SPAD 40                         // bf16 per smem row (32 + 8 pad) -> 80B
#define TILE_BYTES (128 * SPAD * 2)     // 10240
#define STG_BYTES  (4 * TILE_BYTES)     // 40960
#define GEMM_SMEM  (2 * STG_BYTES)      // 81920

__global__ void __launch_bounds__(256) gemm_bf16x3(
    const __nv_bfloat16* __restrict__ Ahi, const __nv_bfloat16* __restrict__ Alo,
    const __nv_bfloat16* __restrict__ Bhi, const __nv_bfloat16* __restrict__ Blo,
    const float* __restrict__ bias, float* __restrict__ C, int M, int N, int K)
{
    extern __shared__ char smem[];
    const uint32_t sbase = smem_u32(smem);
    const int tid  = threadIdx.x;
    const int wid  = tid >> 5;
    const int lane = tid & 31;
    const int m0 = blockIdx.y * GBM;
    const int n0 = blockIdx.x * GBN;
    const int wm = (wid & 1) * 64;      // warp m offset
    const int wn = (wid >> 1) * 32;     // warp n offset

    float acc[4][4][4];
#pragma unroll
    for (int i = 0; i < 4; i++)
#pragma unroll
        for (int j = 0; j < 4; j++)
#pragma unroll
            for (int c = 0; c < 4; c++) acc[i][j][c] = 0.f;

    const __nv_bfloat16* gsrc[4] = {Ahi, Alo, Bhi, Blo};

    // stage loader: 2048 x 16B chunks, 8 per thread
    auto load_stage = [&](int s, int k0) {
        const uint32_t st = sbase + s * STG_BYTES;
#pragma unroll
        for (int t = 0; t < 8; t++) {
            int c = tid + t * 256;              // 0..2047
            int tile = c >> 9;                  // 0:Ahi 1:Alo 2:Bhi 3:Blo
            int w = c & 511;
            int row = w >> 2;
            int col16 = w & 3;
            int grow;
            if (tile < 2) { grow = m0 + row; if (grow >= M) grow = M - 1; }
            else          { grow = n0 + row; }
            const __nv_bfloat16* gp = gsrc[tile] + (size_t)grow * K + k0 + col16 * 8;
            cp16(st + tile * TILE_BYTES + row * (SPAD * 2) + col16 * 16, gp);
        }
    };

    const int nchunk = K / GBK;    // 64
    load_stage(0, 0);
    CP_COMMIT();

    for (int it = 0; it < nchunk; it++) {
        const int buf = it & 1;
        if (it + 1 < nchunk) {
            load_stage(buf ^ 1, (it + 1) * GBK);
            CP_COMMIT();
            CP_WAIT1();
        } else {
            CP_WAIT0();
        }
        __syncthreads();

        const uint32_t st = sbase + buf * STG_BYTES;
        const uint32_t sAh = st;
        const uint32_t sAl = st + TILE_BYTES;
        const uint32_t sBh = st + 2 * TILE_BYTES;
        const uint32_t sBl = st + 3 * TILE_BYTES;
        const int lrow = lane & 15;
        const int lcol = (lane >> 4) * 8;

#pragma unroll
        for (int ks = 0; ks < 2; ks++) {
            const int kb = (ks * 16 + lcol) * 2;    // byte offset in row
            uint32_t ah[4][4], al[4][4], bh[2][4], bl[2][4];
#pragma unroll
            for (int mi = 0; mi < 4; mi++) {
                uint32_t ro = (uint32_t)((wm + mi * 16 + lrow) * (SPAD * 2) + kb);
                ldsm4(ah[mi][0], ah[mi][1], ah[mi][2], ah[mi][3], sAh + ro);
                ldsm4(al[mi][0], al[mi][1], al[mi][2], al[mi][3], sAl + ro);
            }
#pragma unroll
            for (int nc = 0; nc < 2; nc++) {
                uint32_t ro = (uint32_t)((wn + nc * 16 + lrow) * (SPAD * 2) + kb);
                ldsm4(bh[nc][0], bh[nc][1], bh[nc][2], bh[nc][3], sBh + ro);
                ldsm4(bl[nc][0], bl[nc][1], bl[nc][2], bl[nc][3], sBl + ro);
            }
#pragma unroll
            for (int mi = 0; mi < 4; mi++) {
#pragma unroll
                for (int nj = 0; nj < 4; nj++) {
                    const int nc = nj >> 1, hf = nj & 1;
                    float* d = acc[mi][nj];
                    mma_bf16(d[0], d[1], d[2], d[3],
                             ah[mi][0], ah[mi][1], ah[mi][2], ah[mi][3],
                             bh[nc][hf], bh[nc][hf + 2]);
                    mma_bf16(d[0], d[1], d[2], d[3],
                             ah[mi][0], ah[mi][1], ah[mi][2], ah[mi][3],
                             bl[nc][hf], bl[nc][hf + 2]);
                    mma_bf16(d[0], d[1], d[2], d[3],
                             al[mi][0], al[mi][1], al[mi][2], al[mi][3],
                             bh[nc][hf], bh[nc][hf + 2]);
                }
            }
        }
        __syncthreads();
    }

    // epilogue: acc tile (mi,nj): rows m0+wm+mi*16+{g, g+8}, cols n0+wn+nj*8+{2t,2t+1}
    const int g = lane >> 2, tg = lane & 3;
#pragma unroll
    for (int mi = 0; mi < 4; mi++) {
#pragma unroll
        for (int nj = 0; nj < 4; nj++) {
            const int col = n0 + wn + nj * 8 + tg * 2;
            const float2 b2 = *(const float2*)(bias + col);
            const int r0 = m0 + wm + mi * 16 + g;
            if (r0 < M) {
                float2 v; v.x = acc[mi][nj][0] + b2.x; v.y = acc[mi][nj][1] + b2.y;
                *(float2*)(C + (size_t)r0 * N + col) = v;
            }
            const int r1 = r0 + 8;
            if (r1 < M) {
                float2 v; v.x = acc[mi][nj][2] + b2.x; v.y = acc[mi][nj][3] + b2.y;
                *(float2*)(C + (size_t)r1 * N + col) = v;
            }
        }
    }
}

// ---------------- batchnorm ----------------
__global__ void k_col_partial(const float* __restrict__ X, float* __restrict__ part, int M, int D) {
    int blk = blockIdx.x;
    int r0 = blk * 128;
    int r1 = min(r0 + 128, M);
    for (int c = threadIdx.x; c < D; c += blockDim.x) {
        float s = 0.f, s2 = 0.f;
        for (int r = r0; r < r1; r++) {
            float v = X[(size_t)r * D + c];
            s += v; s2 += v * v;
        }
        part[(size_t)(2 * blk) * D + c] = s;
        part[(size_t)(2 * blk + 1) * D + c] = s2;
    }
}
__global__ void k_col_finalize(const float* __restrict__ part, int nblk, int M, int D,
                               float* __restrict__ mu, float* __restrict__ rstd) {
    int c = blockIdx.x * blockDim.x + threadIdx.x;
    if (c >= D) return;
    float s = 0.f, s2 = 0.f;
    for (int b = 0; b < nblk; b++) {
        s  += part[(size_t)(2 * b) * D + c];
        s2 += part[(size_t)(2 * b + 1) * D + c];
    }
    float m = s / M;
    float var = s2 / M - m * m;
    mu[c] = m;
    rstd[c] = rsqrtf(var + 1e-5f);
}
__global__ void k_bn_apply(const float* __restrict__ X, const float* __restrict__ mu,
                           const float* __restrict__ rstd, const float* __restrict__ g,
                           const float* __restrict__ b, float* __restrict__ Y, int n, int D) {
    int i = blockIdx.x * blockDim.x + threadIdx.x;
    if (i >= n) return;
    int c = i & (D - 1);
    Y[i] = (X[i] - mu[c]) * rstd[c] * g[c] + b[c];
}

// ---------------- x assembly + pair gather/split ----------------
__global__ void k_pair_argmax(const int* __restrict__ sp, const int* __restrict__ dp,
                              int* __restrict__ ps, int* __restrict__ pd, int P) {
    int p = blockIdx.x * blockDim.x + threadIdx.x;
    if (p >= P) return;
    atomicMax(&ps[sp[p]], p);
    atomicMax(&pd[dp[p]], p);
}

__global__ void k_assemble_x(const float* __restrict__ bnx, const float* __restrict__ h1c,
                             const float* __restrict__ h2c, const int* __restrict__ ps,
                             const int* __restrict__ pd, float* __restrict__ xout) {
    int i = blockIdx.x * blockDim.x + threadIdx.x;
    if (i >= N_NODES * 1024) return;
    int node = i >> 10, j = i & 1023;
    float v;
    if (j < 512) {
        int d = pd[node];
        if (d >= 0) v = h2c[(size_t)d * 512 + j];
        else {
            int s = ps[node];
            v = (s >= 0) ? h1c[(size_t)s * 512 + j] : bnx[(size_t)node * 512 + j];
        }
    } else {
        v = bnx[(size_t)node * 512 + (j - 512)];
    }
    xout[i] = v;
}

// gather z = [x[src] | x[dst]] directly into split-bf16 hi/lo arrays
__global__ void k_gather_split(const float* __restrict__ xout, const int* __restrict__ sp,
                               const int* __restrict__ dp,
                               __nv_bfloat16* __restrict__ zhi, __nv_bfloat16* __restrict__ zlo) {
    long long i4 = (long long)blockIdx.x * blockDim.x + threadIdx.x;
    if (i4 >= (long long)P_PAIRS * D4 / 4) return;
    long long i = i4 * 4;
    int p = (int)(i >> 11), j = (int)(i & 2047);
    int node = (j < 1024) ? sp[p] : dp[p];
    float4 v = *(const float4*)(xout + (size_t)node * 1024 + (j & 1023));
    __nv_bfloat16 h0, l0, h1, l1, h2, l2, h3, l3;
    split1(v.x, h0, l0); split1(v.y, h1, l1); split1(v.z, h2, l2); split1(v.w, h3, l3);
    *(__nv_bfloat162*)(zhi + i)     = __nv_bfloat162(h0, h1);
    *(__nv_bfloat162*)(zhi + i + 2) = __nv_bfloat162(h2, h3);
    *(__nv_bfloat162*)(zlo + i)     = __nv_bfloat162(l0, l1);
    *(__nv_bfloat162*)(zlo + i + 2) = __nv_bfloat162(l2, l3);
}

__global__ void k_split_w(const float* __restrict__ W,
                          __nv_bfloat16* __restrict__ whi, __nv_bfloat16* __restrict__ wlo, int n4) {
    int i4 = blockIdx.x * blockDim.x + threadIdx.x;
    if (i4 >= n4) return;
    long long i = (long long)i4 * 4;
    float4 v = *(const float4*)(W + i);
    __nv_bfloat16 h0, l0, h1, l1, h2, l2, h3, l3;
    split1(v.x, h0, l0); split1(v.y, h1, l1); split1(v.z, h2, l2); split1(v.w, h3, l3);
    *(__nv_bfloat162*)(whi + i)     = __nv_bfloat162(h0, h1);
    *(__nv_bfloat162*)(whi + i + 2) = __nv_bfloat162(h2, h3);
    *(__nv_bfloat162*)(wlo + i)     = __nv_bfloat162(l0, l1);
    *(__nv_bfloat162*)(wlo + i + 2) = __nv_bfloat162(l2, l3);
}

// ---------------- row layernorm + relu (in place) ----------------
template <int VPT>
__global__ void __launch_bounds__(256) k_row_ln_relu(float* __restrict__ X,
                                                     const float* __restrict__ g,
                                                     const float* __restrict__ b, int W) {
    int row = blockIdx.x;
    float* xr = X + (size_t)row * W;
    float v[VPT];
    float s = 0.f, s2 = 0.f;
#pragma unroll
    for (int i = 0; i < VPT; i++) {
        v[i] = xr[threadIdx.x + i * 256];
        s += v[i]; s2 += v[i] * v[i];
    }
#pragma unroll
    for (int o = 16; o > 0; o >>= 1) {
        s  += __shfl_xor_sync(0xffffffffu, s, o);
        s2 += __shfl_xor_sync(0xffffffffu, s2, o);
    }
    __shared__ float sh[16];
    int warp = threadIdx.x >> 5, lane = threadIdx.x & 31;
    if (lane == 0) { sh[warp] = s; sh[warp + 8] = s2; }
    __syncthreads();
    s = 0.f; s2 = 0.f;
#pragma unroll
    for (int w = 0; w < 8; w++) { s += sh[w]; s2 += sh[w + 8]; }
    float mu = s / W;
    float var = s2 / W - mu * mu;
    float rs = rsqrtf(var + 1e-5f);
#pragma unroll
    for (int i = 0; i < VPT; i++) {
        int c = threadIdx.x + i * 256;
        float y = (v[i] - mu) * rs * g[c] + b[c];
        xr[c] = fmaxf(y, 0.f);
    }
}

// ---------------- launcher ----------------
#define LP1D(kern, n, ...) kern<<<((int)(((long long)(n) + 255) / 256)), 256>>>(__VA_ARGS__)

static inline void* sym(const void* s) {
    void* p = nullptr;
    cudaGetSymbolAddress(&p, s);
    return p;
}

extern "C" void kernel_launch(void* const* d_in, const int* in_sizes, int n_in,
                              void* d_out, int out_size) {
    const float* x_feat = (const float*)d_in[0];
    const int*   edge   = (const int*)d_in[1];
    const int*   pairs  = (const int*)d_in[2];
    const float* h1c    = (const float*)d_in[3];
    const float* h2c    = (const float*)d_in[4];
    const float* W1l = (const float*)d_in[5];
    const float* b1l = (const float*)d_in[6];
    const float* W1r = (const float*)d_in[7];
    const float* bn1_g = (const float*)d_in[8];
    const float* bn1_b = (const float*)d_in[9];
    const float* W2l = (const float*)d_in[10];
    const float* b2l = (const float*)d_in[11];
    const float* W2r = (const float*)d_in[12];
    const float* bn_g = (const float*)d_in[13];
    const float* bn_b = (const float*)d_in[14];
    const float* Wp  = (const float*)d_in[15];
    const float* bp  = (const float*)d_in[16];
    const float* pln_g = (const float*)d_in[17];
    const float* pln_b = (const float*)d_in[18];
    const float* Wpc = (const float*)d_in[19];
    const float* bpc = (const float*)d_in[20];
    const float* We  = (const float*)d_in[21];
    const float* be  = (const float*)d_in[22];
    const float* Wnm = (const float*)d_in[23];
    const float* bnm = (const float*)d_in[24];
    const float* nln_g = (const float*)d_in[25];
    const float* nln_b = (const float*)d_in[26];
    const float* Wnc = (const float*)d_in[27];
    const float* bnc = (const float*)d_in[28];

    const int* e_src = edge;
    const int* e_dst = edge + E_EDGES;
    const int* p_src = pairs;
    const int* p_dst = pairs + P_PAIRS;

    float* out = (float*)d_out;
    float* out_nl  = out;                  // node_logit   [10000,40]
    float* out_pl  = out + 400000;         // pairs_logit  [20000,40]
    float* out_pcl = out + 1200000;        // pairs_cons   [20000,2]
    float* out_x   = out + 1240000;        // x            [10000,1024]
    float* out_gx  = out + 11480000;       // gnn_x        [10000,512]

    unsigned* aggU = (unsigned*)sym(g_aggU);
    float* agg  = (float*)sym(g_agg);
    float* h    = (float*)sym(g_h);
    float* bnx  = (float*)sym(g_bnx);
    float* tbuf = (float*)sym(g_t);
    float* zz   = (float*)sym(g_zz);
    float* part = (float*)sym(g_part);
    float* mu   = (float*)sym(g_mu);
    float* rstd = (float*)sym(g_rstd);
    int* ps = (int*)sym(g_ps);
    int* pd = (int*)sym(g_pd);
    __nv_bfloat16* zhi  = (__nv_bfloat16*)sym(g_zhi);
    __nv_bfloat16* zlo  = (__nv_bfloat16*)sym(g_zlo);
    __nv_bfloat16* wphi = (__nv_bfloat16*)sym(g_wphi);
    __nv_bfloat16* wplo = (__nv_bfloat16*)sym(g_wplo);

    cudaFuncSetAttribute(gemm_bf16x3, cudaFuncAttributeMaxDynamicSharedMemorySize, GEMM_SMEM);

    const int nblk_stats = (N_NODES + 127) / 128;  // 79

    // weight split for big GEMM
    LP1D(k_split_w, D4 * D4 / 4, Wp, wphi, wplo, D4 * D4 / 4);

    // ---- SAGE layer 1 ----
    cudaMemsetAsync(aggU, 0x00, (size_t)N_NODES * D_IN * sizeof(unsigned));
    LP1D(k_scatter_max4, (long long)E_EDGES * (D_IN / 4), x_feat, e_src, e_dst, aggU, E_EDGES, D_IN);
    LP1D(k_decode, N_NODES * D_IN, aggU, agg, N_NODES * D_IN);
    {
        dim3 grid((D_H + 127) / 128, (N_NODES + 127) / 128);
        sgemm_nt<<<grid, 256>>>(agg,    W1l, b1l,     h, N_NODES, D_H, D_IN, 0);
        sgemm_nt<<<grid, 256>>>(x_feat, W1r, nullptr, h, N_NODES, D_H, D_IN, 1);
    }
    k_col_partial<<<nblk_stats, 256>>>(h, part, N_NODES, D_H);
    k_col_finalize<<<2, 256>>>(part, nblk_stats, N_NODES, D_H, mu, rstd);
    LP1D(k_bn_apply, N_NODES * D_H, h, mu, rstd, bn1_g, bn1_b, h, N_NODES * D_H, D_H);

    // ---- SAGE layer 2 ----
    cudaMemsetAsync(aggU, 0x00, (size_t)N_NODES * D_H * sizeof(unsigned));
    LP1D(k_scatter_max4, (long long)E_EDGES * (D_H / 4), h, e_src, e_dst, aggU, E_EDGES, D_H);
    LP1D(k_decode, N_NODES * D_H, aggU, agg, N_NODES * D_H);
    {
        dim3 grid((D_H + 127) / 128, (N_NODES + 127) / 128);
        sgemm_nt<<<grid, 256>>>(agg, W2l, b2l,     out_gx, N_NODES, D_H, D_H, 0);
        sgemm_nt<<<grid, 256>>>(h,   W2r, nullptr, out_gx, N_NODES, D_H, D_H, 1);
    }
    k_col_partial<<<nblk_stats, 256>>>(out_gx, part, N_NODES, D_H);
    k_col_finalize<<<2, 256>>>(part, nblk_stats, N_NODES, D_H, mu, rstd);
    LP1D(k_bn_apply, N_NODES * D_H, out_gx, mu, rstd, bn_g, bn_b, bnx, N_NODES * D_H, D_H);

    // ---- x assembly ----
    cudaMemsetAsync(ps, 0xFF, N_NODES * sizeof(int));
    cudaMemsetAsync(pd, 0xFF, N_NODES * sizeof(int));
    LP1D(k_pair_argmax, P_PAIRS, p_src, p_dst, ps, pd, P_PAIRS);
    LP1D(k_assemble_x, N_NODES * 1024, bnx, h1c, h2c, ps, pd, out_x);

    // ---- pair head ----
    LP1D(k_gather_split, (long long)P_PAIRS * D4 / 4, out_x, p_src, p_dst, zhi, zlo);
    {
        dim3 grid(D4 / GBN, (P_PAIRS + GBM - 1) / GBM);   // (16, 157)
        gemm_bf16x3<<<grid, 256, GEMM_SMEM>>>(zhi, zlo, wphi, wplo, bp, zz, P_PAIRS, D4, D4);
    }
    k_row_ln_relu<8><<<P_PAIRS, 256>>>(zz, pln_g, pln_b, D4);
    {
        dim3 grid(1, (P_PAIRS + 127) / 128);
        sgemm_nt<<<grid, 256>>>(zz, Wpc, bpc, out_pl,  P_PAIRS, NCLS, D4, 0);
        sgemm_nt<<<grid, 256>>>(zz, We,  be,  out_pcl, P_PAIRS, 2,    D4, 0);
    }

    // ---- node head ----
    {
        dim3 grid((D_H + 127) / 128, (N_NODES + 127) / 128);
        sgemm_nt<<<grid, 256>>>(out_x, Wnm, bnm, tbuf, N_NODES, D_H, 1024, 0);
    }
    k_row_ln_relu<2><<<N_NODES, 256>>>(tbuf, nln_g, nln_b, D_H);
    {
        dim3 grid(1, (N_NODES + 127) / 128);
        sgemm_nt<<<grid, 256>>>(tbuf, Wnc, bnc, out_nl, N_NODES, NCLS, D_H, 0);
    }
}